// round 5
// baseline (speedup 1.0000x reference)
#include <cuda_runtime.h>
#include <cuda_fp16.h>
#include <cstdint>
#include <math.h>

#define NPTS 50000
#define KNB  16
#define HALF 64
#define DIM  128
#define TILE_ROWS 128            // 8 points x 16 neighbors
#define TILES8 (NPTS / 8)        // 6250
#define RS    272                // smem row stride bytes (136 fp16: 128 + 8 pad)

// ---------------- scratch (__device__ globals; no allocs allowed) -------
__device__ float g_p0[NPTS * HALF];
__device__ float g_p1[NPTS * HALF];
__device__ float g_pl[NPTS * HALF];

// ---------------- smem map (bytes): 4 x (128 x 136 fp16) tiles + biases --
#define OFF_WA  0
#define OFF_WB  34816
#define OFF_FHI 69632
#define OFF_FLO 104448
#define OFF_BA  139264
#define OFF_BB  139776
#define SMEM_BYTES 140288

// ---------------- helpers ----------------
static __device__ __forceinline__ uint32_t smem_to_u32(const void* p) {
    uint32_t a;
    asm("{ .reg .u64 t; cvta.to.shared.u64 t, %1; cvt.u32.u64 %0, t; }" : "=r"(a) : "l"(p));
    return a;
}
static __device__ __forceinline__ void ldsm_x4(uint32_t* r, uint32_t addr) {
    asm volatile("ldmatrix.sync.aligned.m8n8.x4.shared.b16 {%0,%1,%2,%3}, [%4];"
        : "=r"(r[0]), "=r"(r[1]), "=r"(r[2]), "=r"(r[3]) : "r"(addr));
}
static __device__ __forceinline__ void mma16816(float* d, const uint32_t* a, const uint32_t* b) {
    asm volatile("mma.sync.aligned.m16n8k16.row.col.f32.f16.f16.f32 "
        "{%0,%1,%2,%3}, {%4,%5,%6,%7}, {%8,%9}, {%0,%1,%2,%3};"
        : "+f"(d[0]), "+f"(d[1]), "+f"(d[2]), "+f"(d[3])
        : "r"(a[0]), "r"(a[1]), "r"(a[2]), "r"(a[3]), "r"(b[0]), "r"(b[1]));
}
static __device__ __forceinline__ float gelu_exact(float x) {
    return 0.5f * x * (1.0f + erff(x * 0.70710678118654752f));
}
// split a pair of fp32 into fp16 hi (packed) + fp32 residuals
static __device__ __forceinline__ uint32_t split_f16(float a, float b, float &ra, float &rb) {
    __half ha = __float2half_rn(a), hb = __float2half_rn(b);
    ra = a - __half2float(ha);
    rb = b - __half2float(hb);
    __half2 p; p.x = ha; p.y = hb;
    return *(uint32_t*)&p;
}
static __device__ __forceinline__ uint32_t pack_f16(float a, float b) {
    __half2 p; p.x = __float2half_rn(a); p.y = __float2half_rn(b);
    return *(uint32_t*)&p;
}

// 2-product GEMM accumulate: acc += Ahi*Whi + Alo*Whi   (W rounded once)
// A bases already include the warp's 16-row offset. W is [n][k] fp16, stride RS.
static __device__ __forceinline__ void gemm_split2(
    uint32_t aHiBase, uint32_t aLoBase, uint32_t wBase,
    int lane, float (&acc)[16][4])
{
    const uint32_t aOff = (uint32_t)(lane & 15) * RS + (uint32_t)(lane >> 4) * 16;
    const uint32_t bOff = ((uint32_t)(lane & 7) + ((uint32_t)(lane >> 4) & 1) * 8) * RS
                        + ((uint32_t)(lane >> 3) & 1) * 16;
#pragma unroll
    for (int ks = 0; ks < 8; ks++) {
        const uint32_t ka = ks * 32;
        uint32_t aHi[4], aLo[4];
        ldsm_x4(aHi, aHiBase + aOff + ka);
        ldsm_x4(aLo, aLoBase + aOff + ka);
#pragma unroll
        for (int ntp = 0; ntp < 8; ntp++) {
            uint32_t bHi[4];
            ldsm_x4(bHi, wBase + bOff + (uint32_t)ntp * 16 * RS + ka);
            mma16816(acc[2 * ntp],     aHi, bHi);
            mma16816(acc[2 * ntp + 1], aHi, bHi + 2);
            mma16816(acc[2 * ntp],     aLo, bHi);
            mma16816(acc[2 * ntp + 1], aLo, bHi + 2);
        }
    }
}

// ---------------- kernel 1: p0 = xyz@W1+b1 ; p1 = p0@W2+b2 ----------------
__global__ void k_p01(const float* __restrict__ xyz, const float* __restrict__ W1,
                      const float* __restrict__ b1, const float* __restrict__ W2,
                      const float* __restrict__ b2) {
    __shared__ float sp0[4][HALF];
    __shared__ float sW2[HALF * HALF];
    const int lp = threadIdx.x >> 6;
    const int c  = threadIdx.x & 63;
    const int i  = blockIdx.x * 4 + lp;

    for (int t = threadIdx.x; t < HALF * HALF; t += 256) sW2[t] = __ldg(&W2[t]);

    float x = xyz[i * 3 + 0], y = xyz[i * 3 + 1], z = xyz[i * 3 + 2];
    float v = fmaf(z, __ldg(&W1[2 * HALF + c]), __ldg(&b1[c]));
    v = fmaf(y, __ldg(&W1[1 * HALF + c]), v);
    v = fmaf(x, __ldg(&W1[0 * HALF + c]), v);
    g_p0[i * HALF + c] = v;
    sp0[lp][c] = v;
    __syncthreads();

    float acc = __ldg(&b2[c]);
#pragma unroll
    for (int e = 0; e < HALF; e++)
        acc = fmaf(sp0[lp][e], sW2[e * HALF + c], acc);
    g_p1[i * HALF + c] = acc;
}

// ---------------- kernel 2: p_local = max_k (p0[knn]-p0) ----------------
__global__ void k_plocal(const int* __restrict__ knn) {
    const int lp = threadIdx.x >> 6;
    const int c  = threadIdx.x & 63;
    const int i  = blockIdx.x * 4 + lp;

    float own = g_p0[i * HALF + c];
    float m = -3.402823466e38f;
#pragma unroll
    for (int k = 0; k < KNB; k++) {
        int j = __ldg(&knn[i * KNB + k]);
        m = fmaxf(m, __ldg(&g_p0[j * HALF + c]) - own);
    }
    g_pl[i * HALF + c] = m;
}

// ---------------- kernel 3: fused edge MLP on mma.sync fp16 2-product ----
__global__ void __launch_bounds__(256, 1)
k_mlp(const int* __restrict__ knn,
      const float* __restrict__ W3a, const float* __restrict__ b3a,
      const float* __restrict__ W3b, const float* __restrict__ b3b,
      float* __restrict__ out) {
    extern __shared__ char smem[];
    const uint32_t sbase = smem_to_u32(smem);
    const int tid  = threadIdx.x;
    const int wid  = tid >> 5;
    const int lane = tid & 31;
    const int warpRow = wid * 16;

    float* sBa = (float*)(smem + OFF_BA);
    float* sBb = (float*)(smem + OFF_BB);

    // ---- load weights, rounded once to fp16, stored [n][k] = W[k][n] ----
    for (int idx = tid; idx < 8192; idx += 256) {
        int n = idx >> 6, ep = idx & 63, k = ep << 1;
        uint32_t off = (uint32_t)n * RS + (uint32_t)k * 2;
        *(uint32_t*)(smem + OFF_WA + off) =
            pack_f16(__ldg(&W3a[k * DIM + n]), __ldg(&W3a[(k + 1) * DIM + n]));
        *(uint32_t*)(smem + OFF_WB + off) =
            pack_f16(__ldg(&W3b[k * DIM + n]), __ldg(&W3b[(k + 1) * DIM + n]));
    }
    if (tid < 128) { sBa[tid] = __ldg(&b3a[tid]); sBb[tid] = __ldg(&b3b[tid]); }
    __syncthreads();

    const uint32_t fHiW = sbase + OFF_FHI + (uint32_t)warpRow * RS;   // warp's A rows
    const uint32_t fLoW = sbase + OFF_FLO + (uint32_t)warpRow * RS;
    const int qr = lane >> 2;            // 0..7  (row within half-tile)
    const int qc = (lane & 3) * 2;       // 0,2,4,6 (col pair within n-tile)

    for (int tile = blockIdx.x; tile < TILES8; tile += gridDim.x) {
        const int i0 = tile * 8;

        // ---- cooperative fill of F hi/lo [128 rows x 128 k] (fp16 split) ----
        for (int idx = tid; idx < 8192; idx += 256) {
            int r = idx >> 6, ep = idx & 63, e = ep << 1;
            int i = i0 + (r >> 4);
            int j = __ldg(&knn[i * KNB + (r & 15)]);
            float2 v;
            if (e < HALF) {
                float2 a = *(const float2*)&g_p1[j * HALF + e];
                float2 b = *(const float2*)&g_p1[i * HALF + e];
                v = make_float2(a.x - b.x, a.y - b.y);
            } else {
                v = *(const float2*)&g_pl[i * HALF + (e - HALF)];
            }
            uint32_t off = (uint32_t)r * RS + (uint32_t)e * 2;
            float r0, r1;
            *(uint32_t*)(smem + OFF_FHI + off) = split_f16(v.x, v.y, r0, r1);
            *(uint32_t*)(smem + OFF_FLO + off) = pack_f16(r0, r1);
        }
        __syncthreads();

        // ---- GEMM1: acc = F @ W3a ----
        float acc[16][4];
#pragma unroll
        for (int t = 0; t < 16; t++) { acc[t][0] = acc[t][1] = acc[t][2] = acc[t][3] = 0.f; }
        gemm_split2(fHiW, fLoW, sbase + OFF_WA, lane, acc);

        // ---- epilogue 1: +b3a, gelu, fp16-split into F buffers (own rows) ----
#pragma unroll
        for (int nt = 0; nt < 16; nt++) {
            int c = nt * 8 + qc;
            float bb0 = sBa[c], bb1 = sBa[c + 1];
            float g0 = gelu_exact(acc[nt][0] + bb0);
            float g1 = gelu_exact(acc[nt][1] + bb1);
            float g2 = gelu_exact(acc[nt][2] + bb0);
            float g3 = gelu_exact(acc[nt][3] + bb1);
            uint32_t o0 = (uint32_t)(warpRow + qr) * RS + (uint32_t)c * 2;
            uint32_t o1 = o0 + 8u * RS;
            float r0, r1;
            *(uint32_t*)(smem + OFF_FHI + o0) = split_f16(g0, g1, r0, r1);
            *(uint32_t*)(smem + OFF_FLO + o0) = pack_f16(r0, r1);
            *(uint32_t*)(smem + OFF_FHI + o1) = split_f16(g2, g3, r0, r1);
            *(uint32_t*)(smem + OFF_FLO + o1) = pack_f16(r0, r1);
        }
        __syncwarp();   // cross-lane visibility for ldmatrix in GEMM2

        // ---- GEMM2: acc = H @ W3b ----
#pragma unroll
        for (int t = 0; t < 16; t++) { acc[t][0] = acc[t][1] = acc[t][2] = acc[t][3] = 0.f; }
        gemm_split2(fHiW, fLoW, sbase + OFF_WB, lane, acc);

        // ---- epilogue 2: +b3b, store ----
        {
            float* obase = out + (size_t)(tile * TILE_ROWS + warpRow) * DIM;
#pragma unroll
            for (int nt = 0; nt < 16; nt++) {
                int c = nt * 8 + qc;
                float bb0 = sBb[c], bb1 = sBb[c + 1];
                *(float2*)(obase + (size_t)qr * DIM + c) =
                    make_float2(acc[nt][0] + bb0, acc[nt][1] + bb1);
                *(float2*)(obase + (size_t)(qr + 8) * DIM + c) =
                    make_float2(acc[nt][2] + bb0, acc[nt][3] + bb1);
            }
        }
        __syncthreads();   // all warps done reading F/H before next fill
    }
}

// ---------------- launch ----------------
extern "C" void kernel_launch(void* const* d_in, const int* in_sizes, int n_in,
                              void* d_out, int out_size) {
    const float* xyz = (const float*)d_in[0];
    const int*   knn = (const int*)d_in[1];
    const float* W1  = (const float*)d_in[2];
    const float* b1  = (const float*)d_in[3];
    const float* W2  = (const float*)d_in[4];
    const float* b2  = (const float*)d_in[5];
    const float* W3a = (const float*)d_in[6];
    const float* b3a = (const float*)d_in[7];
    const float* W3b = (const float*)d_in[8];
    const float* b3b = (const float*)d_in[9];
    float* out = (float*)d_out;

    k_p01<<<NPTS / 4, 256>>>(xyz, W1, b1, W2, b2);
    k_plocal<<<NPTS / 4, 256>>>(knn);

    cudaFuncSetAttribute(k_mlp, cudaFuncAttributeMaxDynamicSharedMemorySize, SMEM_BYTES);
    int dev = 0, sms = 148;
    cudaGetDevice(&dev);
    cudaDeviceGetAttribute(&sms, cudaDevAttrMultiProcessorCount, dev);
    k_mlp<<<sms, 256, SMEM_BYTES>>>(knn, W3a, b3a, W3b, b3b, out);
}

// round 6
// speedup vs baseline: 1.1061x; 1.1061x over previous
#include <cuda_runtime.h>
#include <cuda_bf16.h>
#include <cstdint>
#include <math.h>

#define NPTS 50000
#define KNB  16
#define HALF 64
#define DIM  128
#define TILE_ROWS 128            // 8 points x 16 neighbors
#define TILES8 (NPTS / 8)        // 6250
#define RS    272                // smem row stride bytes (136 bf16: 128 + 8 pad)

// ---------------- scratch (__device__ globals; no allocs allowed) -------
__device__ float g_p0[NPTS * HALF];
__device__ float g_p1[NPTS * HALF];
__device__ float g_pl[NPTS * HALF];
__device__ float g_u [NPTS * DIM];   // p1 @ W3a_top
__device__ float g_cc[NPTS * DIM];   // b3a - u + p_local @ W3a_bot

// ---------------- k_mlp smem map (bytes) ----------------
#define OFF_WB_HI 0
#define OFF_WB_LO 34816
#define OFF_HHI   69632
#define OFF_HLO   104448
#define OFF_BB    139264
#define SMEM_BYTES 139776

// ---------------- helpers ----------------
static __device__ __forceinline__ uint32_t smem_to_u32(const void* p) {
    uint32_t a;
    asm("{ .reg .u64 t; cvta.to.shared.u64 t, %1; cvt.u32.u64 %0, t; }" : "=r"(a) : "l"(p));
    return a;
}
static __device__ __forceinline__ void ldsm_x4(uint32_t* r, uint32_t addr) {
    asm volatile("ldmatrix.sync.aligned.m8n8.x4.shared.b16 {%0,%1,%2,%3}, [%4];"
        : "=r"(r[0]), "=r"(r[1]), "=r"(r[2]), "=r"(r[3]) : "r"(addr));
}
static __device__ __forceinline__ void mma16816(float* d, const uint32_t* a, const uint32_t* b) {
    asm volatile("mma.sync.aligned.m16n8k16.row.col.f32.bf16.bf16.f32 "
        "{%0,%1,%2,%3}, {%4,%5,%6,%7}, {%8,%9}, {%0,%1,%2,%3};"
        : "+f"(d[0]), "+f"(d[1]), "+f"(d[2]), "+f"(d[3])
        : "r"(a[0]), "r"(a[1]), "r"(a[2]), "r"(a[3]), "r"(b[0]), "r"(b[1]));
}
static __device__ __forceinline__ float gelu_exact(float x) {
    return 0.5f * x * (1.0f + erff(x * 0.70710678118654752f));
}
static __device__ __forceinline__ uint32_t split_hi2(float a, float b, float &ra, float &rb) {
    __nv_bfloat16 ha = __float2bfloat16_rn(a), hb = __float2bfloat16_rn(b);
    ra = a - __bfloat162float(ha);
    rb = b - __bfloat162float(hb);
    __nv_bfloat162 p; p.x = ha; p.y = hb;
    return *(uint32_t*)&p;
}
static __device__ __forceinline__ uint32_t pack_bf2(float a, float b) {
    __nv_bfloat162 p; p.x = __float2bfloat16_rn(a); p.y = __float2bfloat16_rn(b);
    return *(uint32_t*)&p;
}

// 3-split GEMM accumulate: acc += Ahi*Bhi + Ahi*Blo + Alo*Bhi
static __device__ __forceinline__ void gemm_split(
    uint32_t aHiBase, uint32_t aLoBase, uint32_t wHiBase, uint32_t wLoBase,
    int lane, float (&acc)[16][4])
{
    const uint32_t aOff = (uint32_t)(lane & 15) * RS + (uint32_t)(lane >> 4) * 16;
    const uint32_t bOff = ((uint32_t)(lane & 7) + ((uint32_t)(lane >> 4) & 1) * 8) * RS
                        + ((uint32_t)(lane >> 3) & 1) * 16;
#pragma unroll
    for (int ks = 0; ks < 8; ks++) {
        const uint32_t ka = ks * 32;
        uint32_t aHi[4], aLo[4];
        ldsm_x4(aHi, aHiBase + aOff + ka);
        ldsm_x4(aLo, aLoBase + aOff + ka);
#pragma unroll
        for (int ntp = 0; ntp < 8; ntp++) {
            uint32_t bHi[4], bLo[4];
            ldsm_x4(bHi, wHiBase + bOff + (uint32_t)ntp * 16 * RS + ka);
            ldsm_x4(bLo, wLoBase + bOff + (uint32_t)ntp * 16 * RS + ka);
            mma16816(acc[2 * ntp],     aHi, bHi);
            mma16816(acc[2 * ntp + 1], aHi, bHi + 2);
            mma16816(acc[2 * ntp],     aHi, bLo);
            mma16816(acc[2 * ntp + 1], aHi, bLo + 2);
            mma16816(acc[2 * ntp],     aLo, bHi);
            mma16816(acc[2 * ntp + 1], aLo, bHi + 2);
        }
    }
}

// ---------------- kernel 1: p0 = xyz@W1+b1 ; p1 = p0@W2+b2 (round-4 ver) --
__global__ void k_p01(const float* __restrict__ xyz, const float* __restrict__ W1,
                      const float* __restrict__ b1, const float* __restrict__ W2,
                      const float* __restrict__ b2) {
    __shared__ float sp0[4][HALF];
    const int lp = threadIdx.x >> 6;
    const int c  = threadIdx.x & 63;
    const int i  = blockIdx.x * 4 + lp;

    float x = xyz[i * 3 + 0], y = xyz[i * 3 + 1], z = xyz[i * 3 + 2];
    float v = fmaf(z, __ldg(&W1[2 * HALF + c]), __ldg(&b1[c]));
    v = fmaf(y, __ldg(&W1[1 * HALF + c]), v);
    v = fmaf(x, __ldg(&W1[0 * HALF + c]), v);
    g_p0[i * HALF + c] = v;
    sp0[lp][c] = v;
    __syncthreads();

    float acc = __ldg(&b2[c]);
#pragma unroll
    for (int e = 0; e < HALF; e++)
        acc = fmaf(sp0[lp][e], __ldg(&W2[e * HALF + c]), acc);
    g_p1[i * HALF + c] = acc;
}

// ---------------- kernel 2: p_local = max_k (p0[knn]-p0) ----------------
__global__ void k_plocal(const int* __restrict__ knn) {
    const int lp = threadIdx.x >> 6;
    const int c  = threadIdx.x & 63;
    const int i  = blockIdx.x * 4 + lp;

    float own = g_p0[i * HALF + c];
    float m = -3.402823466e38f;
#pragma unroll
    for (int k = 0; k < KNB; k++) {
        int j = __ldg(&knn[i * KNB + k]);
        m = fmaxf(m, __ldg(&g_p0[j * HALF + c]) - own);
    }
    g_pl[i * HALF + c] = m;
}

// ---------------- kernel 2b: u = p1@Wtop ; cc = b3a - u + pl@Wbot --------
// 16 points per block, 256 threads. Exact fp32.
__global__ void __launch_bounds__(256)
k_uc(const float* __restrict__ W3a, const float* __restrict__ b3a) {
    extern __shared__ float us[];
    float* sW  = us;            // 16384 (W3a row-major [e][c])
    float* sp1 = us + 16384;    // 16 x 64
    float* spl = sp1 + 1024;    // 16 x 64
    float* sb  = spl + 1024;    // 128

    const int tid  = threadIdx.x;
    const int base = blockIdx.x * 16;

    for (int t = tid; t < 16384; t += 256) sW[t] = __ldg(&W3a[t]);
    for (int t = tid; t < 1024; t += 256) {
        int p = t >> 6, e = t & 63;
        sp1[t] = g_p1[(base + p) * HALF + e];
        spl[t] = g_pl[(base + p) * HALF + e];
    }
    if (tid < 128) sb[tid] = __ldg(&b3a[tid]);
    __syncthreads();

    const int c  = tid & 127;
    const int ph = (tid >> 7) * 8;

    float aU[8], aC[8];
#pragma unroll
    for (int pp = 0; pp < 8; pp++) { aU[pp] = 0.f; aC[pp] = sb[c]; }
#pragma unroll 8
    for (int e = 0; e < HALF; e++) {
        float w1 = sW[e * DIM + c];
        float w2 = sW[(HALF + e) * DIM + c];
#pragma unroll
        for (int pp = 0; pp < 8; pp++) {
            aU[pp] = fmaf(sp1[(ph + pp) * HALF + e], w1, aU[pp]);
            aC[pp] = fmaf(spl[(ph + pp) * HALF + e], w2, aC[pp]);
        }
    }
#pragma unroll
    for (int pp = 0; pp < 8; pp++) {
        size_t idx = (size_t)(base + ph + pp) * DIM + c;
        g_u[idx]  = aU[pp];
        g_cc[idx] = aC[pp] - aU[pp];
    }
}

// ---------------- kernel 3: gather+GELU -> GEMM2 (bf16 3-split) ----------
__global__ void __launch_bounds__(256, 1)
k_mlp(const int* __restrict__ knn,
      const float* __restrict__ W3b, const float* __restrict__ b3b,
      float* __restrict__ out) {
    extern __shared__ char smem[];
    const uint32_t sbase = smem_to_u32(smem);
    const int tid  = threadIdx.x;
    const int wid  = tid >> 5;
    const int lane = tid & 31;
    const int warpRow = wid * 16;

    float* sBb = (float*)(smem + OFF_BB);

    // ---- load + split W3b (stored [n][k] = W[k][n], bf16 hi/lo) ----
    for (int idx = tid; idx < 8192; idx += 256) {
        int n = idx >> 6, ep = idx & 63, k = ep << 1;
        uint32_t off = (uint32_t)n * RS + (uint32_t)k * 2;
        float b0 = __ldg(&W3b[k * DIM + n]);
        float b1v = __ldg(&W3b[(k + 1) * DIM + n]);
        float rb0, rb1;
        *(uint32_t*)(smem + OFF_WB_HI + off) = split_hi2(b0, b1v, rb0, rb1);
        *(uint32_t*)(smem + OFF_WB_LO + off) = pack_bf2(rb0, rb1);
    }
    if (tid < 128) sBb[tid] = __ldg(&b3b[tid]);
    __syncthreads();

    const uint32_t hHiW = sbase + OFF_HHI + (uint32_t)warpRow * RS;
    const uint32_t hLoW = sbase + OFF_HLO + (uint32_t)warpRow * RS;
    const int qr = lane >> 2;
    const int qc = (lane & 3) * 2;

    for (int tile = blockIdx.x; tile < TILES8; tile += gridDim.x) {
        const int i0 = tile * 8;

        // ---- fill H hi/lo: h = gelu(u[knn] + cc[i]) over 128x128 ----
        for (int idx = tid; idx < 8192; idx += 256) {
            int r = idx >> 6, ep = idx & 63, e = ep << 1;
            int i = i0 + (r >> 4);
            int j = __ldg(&knn[i * KNB + (r & 15)]);
            float2 uu = *(const float2*)&g_u[(size_t)j * DIM + e];
            float2 cv = *(const float2*)&g_cc[(size_t)i * DIM + e];
            float g0 = gelu_exact(uu.x + cv.x);
            float g1 = gelu_exact(uu.y + cv.y);
            uint32_t off = (uint32_t)r * RS + (uint32_t)e * 2;
            float r0, r1;
            *(uint32_t*)(smem + OFF_HHI + off) = split_hi2(g0, g1, r0, r1);
            *(uint32_t*)(smem + OFF_HLO + off) = pack_bf2(r0, r1);
        }
        __syncthreads();

        // ---- GEMM2: acc = H @ W3b ----
        float acc[16][4];
#pragma unroll
        for (int t = 0; t < 16; t++) { acc[t][0] = acc[t][1] = acc[t][2] = acc[t][3] = 0.f; }
        gemm_split(hHiW, hLoW, sbase + OFF_WB_HI, sbase + OFF_WB_LO, lane, acc);

        // ---- epilogue: +b3b, store ----
        {
            float* obase = out + (size_t)(tile * TILE_ROWS + warpRow) * DIM;
#pragma unroll
            for (int nt = 0; nt < 16; nt++) {
                int c = nt * 8 + qc;
                float bb0 = sBb[c], bb1 = sBb[c + 1];
                *(float2*)(obase + (size_t)qr * DIM + c) =
                    make_float2(acc[nt][0] + bb0, acc[nt][1] + bb1);
                *(float2*)(obase + (size_t)(qr + 8) * DIM + c) =
                    make_float2(acc[nt][2] + bb0, acc[nt][3] + bb1);
            }
        }
        __syncthreads();   // all warps done reading H before next fill
    }
}

// ---------------- launch ----------------
extern "C" void kernel_launch(void* const* d_in, const int* in_sizes, int n_in,
                              void* d_out, int out_size) {
    const float* xyz = (const float*)d_in[0];
    const int*   knn = (const int*)d_in[1];
    const float* W1  = (const float*)d_in[2];
    const float* b1  = (const float*)d_in[3];
    const float* W2  = (const float*)d_in[4];
    const float* b2  = (const float*)d_in[5];
    const float* W3a = (const float*)d_in[6];
    const float* b3a = (const float*)d_in[7];
    const float* W3b = (const float*)d_in[8];
    const float* b3b = (const float*)d_in[9];
    float* out = (float*)d_out;

    k_p01<<<NPTS / 4, 256>>>(xyz, W1, b1, W2, b2);
    k_plocal<<<NPTS / 4, 256>>>(knn);

    cudaFuncSetAttribute(k_uc, cudaFuncAttributeMaxDynamicSharedMemorySize, 74240);
    k_uc<<<NPTS / 16, 256, 74240>>>(W3a, b3a);

    cudaFuncSetAttribute(k_mlp, cudaFuncAttributeMaxDynamicSharedMemorySize, SMEM_BYTES);
    int dev = 0, sms = 148;
    cudaGetDevice(&dev);
    cudaDeviceGetAttribute(&sms, cudaDevAttrMultiProcessorCount, dev);
    k_mlp<<<sms, 256, SMEM_BYTES>>>(knn, W3b, b3b, out);
}

// round 7
// speedup vs baseline: 2.3614x; 2.1348x over previous
#include <cuda_runtime.h>
#include <cuda_bf16.h>
#include <cstdint>
#include <math.h>

#define NPTS 50000
#define KNB  16
#define HALF 64
#define DIM  128
#define TILE_ROWS 128            // 8 points x 16 neighbors
#define TILES8 (NPTS / 8)        // 6250
#define RS    272                // smem row stride bytes (136 bf16: 128 + 8 pad)

// ---------------- scratch (__device__ globals; no allocs allowed) -------
__device__ float g_p0[NPTS * HALF];
__device__ float g_p1[NPTS * HALF];
__device__ float g_pl[NPTS * HALF];
__device__ float g_u [NPTS * DIM];   // p1 @ W3a_top
__device__ float g_cc[NPTS * DIM];   // b3a - u + p_local @ W3a_bot

// ---------------- k_mlp smem map (bytes) ----------------
#define OFF_WB_HI 0
#define OFF_WB_LO 34816
#define OFF_BB    69632
#define SMEM_BYTES 70144

// ---------------- helpers ----------------
static __device__ __forceinline__ uint32_t smem_to_u32(const void* p) {
    uint32_t a;
    asm("{ .reg .u64 t; cvta.to.shared.u64 t, %1; cvt.u32.u64 %0, t; }" : "=r"(a) : "l"(p));
    return a;
}
static __device__ __forceinline__ void ldsm_x4(uint32_t* r, uint32_t addr) {
    asm volatile("ldmatrix.sync.aligned.m8n8.x4.shared.b16 {%0,%1,%2,%3}, [%4];"
        : "=r"(r[0]), "=r"(r[1]), "=r"(r[2]), "=r"(r[3]) : "r"(addr));
}
static __device__ __forceinline__ void mma16816(float* d, const uint32_t* a, const uint32_t* b) {
    asm volatile("mma.sync.aligned.m16n8k16.row.col.f32.bf16.bf16.f32 "
        "{%0,%1,%2,%3}, {%4,%5,%6,%7}, {%8,%9}, {%0,%1,%2,%3};"
        : "+f"(d[0]), "+f"(d[1]), "+f"(d[2]), "+f"(d[3])
        : "r"(a[0]), "r"(a[1]), "r"(a[2]), "r"(a[3]), "r"(b[0]), "r"(b[1]));
}
static __device__ __forceinline__ float gelu_exact(float x) {
    return 0.5f * x * (1.0f + erff(x * 0.70710678118654752f));
}
static __device__ __forceinline__ uint32_t split_hi2(float a, float b, float &ra, float &rb) {
    __nv_bfloat16 ha = __float2bfloat16_rn(a), hb = __float2bfloat16_rn(b);
    ra = a - __bfloat162float(ha);
    rb = b - __bfloat162float(hb);
    __nv_bfloat162 p; p.x = ha; p.y = hb;
    return *(uint32_t*)&p;
}
static __device__ __forceinline__ uint32_t pack_bf2(float a, float b) {
    __nv_bfloat162 p; p.x = __float2bfloat16_rn(a); p.y = __float2bfloat16_rn(b);
    return *(uint32_t*)&p;
}

// ---------------- kernel 1: p0 = xyz@W1+b1 ; p1 = p0@W2+b2 ----------------
__global__ void k_p01(const float* __restrict__ xyz, const float* __restrict__ W1,
                      const float* __restrict__ b1, const float* __restrict__ W2,
                      const float* __restrict__ b2) {
    __shared__ float sp0[4][HALF];
    const int lp = threadIdx.x >> 6;
    const int c  = threadIdx.x & 63;
    const int i  = blockIdx.x * 4 + lp;

    float x = xyz[i * 3 + 0], y = xyz[i * 3 + 1], z = xyz[i * 3 + 2];
    float v = fmaf(z, __ldg(&W1[2 * HALF + c]), __ldg(&b1[c]));
    v = fmaf(y, __ldg(&W1[1 * HALF + c]), v);
    v = fmaf(x, __ldg(&W1[0 * HALF + c]), v);
    g_p0[i * HALF + c] = v;
    sp0[lp][c] = v;
    __syncthreads();

    float acc = __ldg(&b2[c]);
#pragma unroll
    for (int e = 0; e < HALF; e++)
        acc = fmaf(sp0[lp][e], __ldg(&W2[e * HALF + c]), acc);
    g_p1[i * HALF + c] = acc;
}

// ---------------- kernel 2: p_local = max_k (p0[knn]-p0) ----------------
__global__ void k_plocal(const int* __restrict__ knn) {
    const int lp = threadIdx.x >> 6;
    const int c  = threadIdx.x & 63;
    const int i  = blockIdx.x * 4 + lp;

    float own = g_p0[i * HALF + c];
    float m = -3.402823466e38f;
#pragma unroll
    for (int k = 0; k < KNB; k++) {
        int j = __ldg(&knn[i * KNB + k]);
        m = fmaxf(m, __ldg(&g_p0[j * HALF + c]) - own);
    }
    g_pl[i * HALF + c] = m;
}

// ---------------- kernel 2b: u = p1@Wtop ; cc = b3a - u + pl@Wbot --------
__global__ void __launch_bounds__(256)
k_uc(const float* __restrict__ W3a, const float* __restrict__ b3a) {
    extern __shared__ float us[];
    float* sW  = us;            // 16384
    float* sp1 = us + 16384;    // 16 x 64
    float* spl = sp1 + 1024;    // 16 x 64
    float* sb  = spl + 1024;    // 128

    const int tid  = threadIdx.x;
    const int base = blockIdx.x * 16;

    for (int t = tid; t < 16384; t += 256) sW[t] = __ldg(&W3a[t]);
    for (int t = tid; t < 1024; t += 256) {
        int p = t >> 6, e = t & 63;
        sp1[t] = g_p1[(base + p) * HALF + e];
        spl[t] = g_pl[(base + p) * HALF + e];
    }
    if (tid < 128) sb[tid] = __ldg(&b3a[tid]);
    __syncthreads();

    const int c  = tid & 127;
    const int ph = (tid >> 7) * 8;

    float aU[8], aC[8];
#pragma unroll
    for (int pp = 0; pp < 8; pp++) { aU[pp] = 0.f; aC[pp] = sb[c]; }
#pragma unroll 8
    for (int e = 0; e < HALF; e++) {
        float w1 = sW[e * DIM + c];
        float w2 = sW[(HALF + e) * DIM + c];
#pragma unroll
        for (int pp = 0; pp < 8; pp++) {
            aU[pp] = fmaf(sp1[(ph + pp) * HALF + e], w1, aU[pp]);
            aC[pp] = fmaf(spl[(ph + pp) * HALF + e], w2, aC[pp]);
        }
    }
#pragma unroll
    for (int pp = 0; pp < 8; pp++) {
        size_t idx = (size_t)(base + ph + pp) * DIM + c;
        g_u[idx]  = aU[pp];
        g_cc[idx] = aC[pp] - aU[pp];
    }
}

// ---------------- kernel 3: register-direct gather+GELU -> GEMM2 ---------
// Each warp owns one point's 16 neighbor-rows. A-fragments built directly
// in registers from global gathers; no per-tile barriers, no A smem.
__global__ void __launch_bounds__(256, 2)
k_mlp(const int* __restrict__ knn,
      const float* __restrict__ W3b, const float* __restrict__ b3b,
      float* __restrict__ out) {
    extern __shared__ char smem[];
    const uint32_t sbase = smem_to_u32(smem);
    const int tid  = threadIdx.x;
    const int wid  = tid >> 5;
    const int lane = tid & 31;

    float* sBb = (float*)(smem + OFF_BB);

    // ---- load + split W3b (stored [n][k] = W[k][n], bf16 hi/lo) ----
    for (int idx = tid; idx < 8192; idx += 256) {
        int n = idx >> 6, ep = idx & 63, k = ep << 1;
        uint32_t off = (uint32_t)n * RS + (uint32_t)k * 2;
        float b0 = __ldg(&W3b[k * DIM + n]);
        float b1v = __ldg(&W3b[(k + 1) * DIM + n]);
        float rb0, rb1;
        *(uint32_t*)(smem + OFF_WB_HI + off) = split_hi2(b0, b1v, rb0, rb1);
        *(uint32_t*)(smem + OFF_WB_LO + off) = pack_bf2(rb0, rb1);
    }
    if (tid < 128) sBb[tid] = __ldg(&b3b[tid]);
    __syncthreads();

    const int qr = lane >> 2;            // fragment row group 0..7
    const int qc = (lane & 3) * 2;       // fragment k/col pair 0,2,4,6
    const uint32_t bOff = ((uint32_t)(lane & 7) + ((uint32_t)(lane >> 4) & 1) * 8) * RS
                        + ((uint32_t)(lane >> 3) & 1) * 16;
    const uint32_t wHi = sbase + OFF_WB_HI + bOff;
    const uint32_t wLo = sbase + OFF_WB_LO + bOff;

    for (int tile = blockIdx.x; tile < TILES8; tile += gridDim.x) {
        const int i = tile * 8 + wid;    // this warp's point

        // distribute this point's 16 neighbor indices via shuffle
        int jj = __ldg(&knn[i * KNB + (lane & 15)]);
        const int j0 = __shfl_sync(0xFFFFFFFF, jj, qr);
        const int j1 = __shfl_sync(0xFFFFFFFF, jj, qr + 8);

        const float* u0 = g_u  + (size_t)j0 * DIM + qc;
        const float* u1 = g_u  + (size_t)j1 * DIM + qc;
        const float* cp = g_cc + (size_t)i  * DIM + qc;

        float acc[16][4];
#pragma unroll
        for (int t = 0; t < 16; t++) { acc[t][0] = acc[t][1] = acc[t][2] = acc[t][3] = 0.f; }

        // prefetch k-step 0
        float2 va0 = *(const float2*)(u0);      float2 va1 = *(const float2*)(u0 + 8);
        float2 vb0 = *(const float2*)(u1);      float2 vb1 = *(const float2*)(u1 + 8);
        float2 vc0 = *(const float2*)(cp);      float2 vc1 = *(const float2*)(cp + 8);

#pragma unroll
        for (int ks = 0; ks < 8; ks++) {
            float2 na0, na1, nb0, nb1, nc0, nc1;
            if (ks < 7) {
                const int kb = (ks + 1) * 16;
                na0 = *(const float2*)(u0 + kb);  na1 = *(const float2*)(u0 + kb + 8);
                nb0 = *(const float2*)(u1 + kb);  nb1 = *(const float2*)(u1 + kb + 8);
                nc0 = *(const float2*)(cp + kb);  nc1 = *(const float2*)(cp + kb + 8);
            }
            // h = gelu(u + cc), split to bf16 hi/lo fragments
            float h00 = gelu_exact(va0.x + vc0.x), h01 = gelu_exact(va0.y + vc0.y);
            float h08 = gelu_exact(va1.x + vc1.x), h09 = gelu_exact(va1.y + vc1.y);
            float h10 = gelu_exact(vb0.x + vc0.x), h11 = gelu_exact(vb0.y + vc0.y);
            float h18 = gelu_exact(vb1.x + vc1.x), h19 = gelu_exact(vb1.y + vc1.y);

            uint32_t aHi[4], aLo[4];
            float r0, r1;
            aHi[0] = split_hi2(h00, h01, r0, r1); aLo[0] = pack_bf2(r0, r1);
            aHi[1] = split_hi2(h10, h11, r0, r1); aLo[1] = pack_bf2(r0, r1);
            aHi[2] = split_hi2(h08, h09, r0, r1); aLo[2] = pack_bf2(r0, r1);
            aHi[3] = split_hi2(h18, h19, r0, r1); aLo[3] = pack_bf2(r0, r1);

            const uint32_t ka = (uint32_t)ks * 32;
#pragma unroll
            for (int ntp = 0; ntp < 8; ntp++) {
                uint32_t bHi[4], bLo[4];
                ldsm_x4(bHi, wHi + (uint32_t)ntp * 16 * RS + ka);
                ldsm_x4(bLo, wLo + (uint32_t)ntp * 16 * RS + ka);
                mma16816(acc[2 * ntp],     aHi, bHi);
                mma16816(acc[2 * ntp + 1], aHi, bHi + 2);
                mma16816(acc[2 * ntp],     aHi, bLo);
                mma16816(acc[2 * ntp + 1], aHi, bLo + 2);
                mma16816(acc[2 * ntp],     aLo, bHi);
                mma16816(acc[2 * ntp + 1], aLo, bHi + 2);
            }
            va0 = na0; va1 = na1; vb0 = nb0; vb1 = nb1; vc0 = nc0; vc1 = nc1;
        }

        // ---- epilogue: +b3b, store (rows qr and qr+8 of this warp) ----
        {
            float* obase = out + ((size_t)i * KNB) * DIM;   // warp's 16 rows
#pragma unroll
            for (int nt = 0; nt < 16; nt++) {
                int c = nt * 8 + qc;
                float bb0 = sBb[c], bb1 = sBb[c + 1];
                *(float2*)(obase + (size_t)qr * DIM + c) =
                    make_float2(acc[nt][0] + bb0, acc[nt][1] + bb1);
                *(float2*)(obase + (size_t)(qr + 8) * DIM + c) =
                    make_float2(acc[nt][2] + bb0, acc[nt][3] + bb1);
            }
        }
    }
}

// ---------------- launch ----------------
extern "C" void kernel_launch(void* const* d_in, const int* in_sizes, int n_in,
                              void* d_out, int out_size) {
    const float* xyz = (const float*)d_in[0];
    const int*   knn = (const int*)d_in[1];
    const float* W1  = (const float*)d_in[2];
    const float* b1  = (const float*)d_in[3];
    const float* W2  = (const float*)d_in[4];
    const float* b2  = (const float*)d_in[5];
    const float* W3a = (const float*)d_in[6];
    const float* b3a = (const float*)d_in[7];
    const float* W3b = (const float*)d_in[8];
    const float* b3b = (const float*)d_in[9];
    float* out = (float*)d_out;

    k_p01<<<NPTS / 4, 256>>>(xyz, W1, b1, W2, b2);
    k_plocal<<<NPTS / 4, 256>>>(knn);

    cudaFuncSetAttribute(k_uc, cudaFuncAttributeMaxDynamicSharedMemorySize, 74240);
    k_uc<<<NPTS / 16, 256, 74240>>>(W3a, b3a);

    cudaFuncSetAttribute(k_mlp, cudaFuncAttributeMaxDynamicSharedMemorySize, SMEM_BYTES);
    int dev = 0, sms = 148;
    cudaGetDevice(&dev);
    cudaDeviceGetAttribute(&sms, cudaDevAttrMultiProcessorCount, dev);
    k_mlp<<<2 * sms, 256, SMEM_BYTES>>>(knn, W3b, b3b, out);
}

// round 8
// speedup vs baseline: 2.4367x; 1.0319x over previous
#include <cuda_runtime.h>
#include <cuda_bf16.h>
#include <cstdint>
#include <math.h>

#define NPTS 50000
#define KNB  16
#define HALF 64
#define DIM  128
#define TILES8 (NPTS / 8)        // 6250
#define RS    272                // smem row stride bytes (136 bf16: 128 + 8 pad)

// ---------------- scratch (__device__ globals; no allocs allowed) -------
__device__ float g_p0[NPTS * HALF];
__device__ float g_p1[NPTS * HALF];
__device__ float g_u [NPTS * DIM];   // p1 @ W3a_top
__device__ float g_cc[NPTS * DIM];   // b3a - u + p_local @ W3a_bot

// ---------------- k_mlp smem map (bytes) ----------------
#define OFF_WB_HI 0
#define OFF_WB_LO 34816
#define OFF_BB    69632
#define SMEM_BYTES 70144

// k_uc smem: 16384 W + 1024 p1 + 1024 pl + 128 b + 256 knn = 18816 floats
#define UC_SMEM_BYTES 75264

// ---------------- helpers ----------------
static __device__ __forceinline__ uint32_t smem_to_u32(const void* p) {
    uint32_t a;
    asm("{ .reg .u64 t; cvta.to.shared.u64 t, %1; cvt.u32.u64 %0, t; }" : "=r"(a) : "l"(p));
    return a;
}
static __device__ __forceinline__ void ldsm_x4(uint32_t* r, uint32_t addr) {
    asm volatile("ldmatrix.sync.aligned.m8n8.x4.shared.b16 {%0,%1,%2,%3}, [%4];"
        : "=r"(r[0]), "=r"(r[1]), "=r"(r[2]), "=r"(r[3]) : "r"(addr));
}
static __device__ __forceinline__ void mma16816(float* d, const uint32_t* a, const uint32_t* b) {
    asm volatile("mma.sync.aligned.m16n8k16.row.col.f32.bf16.bf16.f32 "
        "{%0,%1,%2,%3}, {%4,%5,%6,%7}, {%8,%9}, {%0,%1,%2,%3};"
        : "+f"(d[0]), "+f"(d[1]), "+f"(d[2]), "+f"(d[3])
        : "r"(a[0]), "r"(a[1]), "r"(a[2]), "r"(a[3]), "r"(b[0]), "r"(b[1]));
}
static __device__ __forceinline__ float gelu_exact(float x) {
    return 0.5f * x * (1.0f + erff(x * 0.70710678118654752f));
}
// truncation split: hi = top-16-bits (exact bf16), residual exact in fp32
static __device__ __forceinline__ uint32_t split_trunc2(float a, float b, float &ra, float &rb) {
    uint32_t ua = __float_as_uint(a) & 0xFFFF0000u;
    uint32_t ub = __float_as_uint(b) & 0xFFFF0000u;
    ra = a - __uint_as_float(ua);
    rb = b - __uint_as_float(ub);
    return __byte_perm(ua, ub, 0x7632);      // [a.hi16 | b.hi16] -> bf16x2 (x=a)
}
static __device__ __forceinline__ uint32_t cvt_bf2(float a, float b) {   // x=a, y=b
    uint32_t r;
    asm("cvt.rn.bf16x2.f32 %0, %1, %2;" : "=r"(r) : "f"(b), "f"(a));
    return r;
}
static __device__ __forceinline__ uint32_t split_rn2(float a, float b, float &ra, float &rb) {
    __nv_bfloat16 ha = __float2bfloat16_rn(a), hb = __float2bfloat16_rn(b);
    ra = a - __bfloat162float(ha);
    rb = b - __bfloat162float(hb);
    __nv_bfloat162 p; p.x = ha; p.y = hb;
    return *(uint32_t*)&p;
}
// even-k pair -> permuted slot (within 16-block): r=4t+2e -> 2t+8e
static __host__ __device__ __forceinline__ int perm_pair(int k) {
    int b = k & ~15, r = k & 15;
    return b + ((r >> 2) << 1) + ((r & 2) << 2);
}

// ---------------- kernel 1: p0 = xyz@W1+b1 ; p1 = p0@W2+b2 ----------------
__global__ void k_p01(const float* __restrict__ xyz, const float* __restrict__ W1,
                      const float* __restrict__ b1, const float* __restrict__ W2,
                      const float* __restrict__ b2) {
    __shared__ float sp0[4][HALF];
    const int lp = threadIdx.x >> 6;
    const int c  = threadIdx.x & 63;
    const int i  = blockIdx.x * 4 + lp;

    float x = xyz[i * 3 + 0], y = xyz[i * 3 + 1], z = xyz[i * 3 + 2];
    float v = fmaf(z, __ldg(&W1[2 * HALF + c]), __ldg(&b1[c]));
    v = fmaf(y, __ldg(&W1[1 * HALF + c]), v);
    v = fmaf(x, __ldg(&W1[0 * HALF + c]), v);
    g_p0[i * HALF + c] = v;
    sp0[lp][c] = v;
    __syncthreads();

    float acc = __ldg(&b2[c]);
#pragma unroll
    for (int e = 0; e < HALF; e++)
        acc = fmaf(sp0[lp][e], __ldg(&W2[e * HALF + c]), acc);
    g_p1[i * HALF + c] = acc;
}

// ---------------- kernel 2: fused p_local + (u, cc) --------------------
// 16 points per block. Phase 1: p_local = max_k(p0[knn]-p0). Phase 2:
// u = p1@Wtop ; cc = b3a - u + p_local@Wbot. Exact fp32.
__global__ void __launch_bounds__(256)
k_uc(const int* __restrict__ knn, const float* __restrict__ W3a,
     const float* __restrict__ b3a) {
    extern __shared__ float us[];
    float* sW   = us;              // 16384
    float* sp1  = us + 16384;      // 16 x 64
    float* spl  = sp1 + 1024;      // 16 x 64
    float* sb   = spl + 1024;      // 128
    int*   sknn = (int*)(sb + 128);// 256

    const int tid  = threadIdx.x;
    const int base = blockIdx.x * 16;

    for (int t = tid; t < 16384; t += 256) sW[t] = __ldg(&W3a[t]);
    if (tid < 128) sb[tid] = __ldg(&b3a[tid]);
    sknn[tid] = __ldg(&knn[base * KNB + tid]);
    for (int t = tid; t < 1024; t += 256) {
        int p = t >> 6, e = t & 63;
        sp1[t] = g_p1[(base + p) * HALF + e];
    }
    __syncthreads();

    // phase 1: p_local
    for (int t = tid; t < 1024; t += 256) {
        int p = t >> 6, c = t & 63;
        float own = g_p0[(base + p) * HALF + c];
        float m = -3.402823466e38f;
#pragma unroll
        for (int k = 0; k < KNB; k++) {
            int j = sknn[p * KNB + k];
            m = fmaxf(m, __ldg(&g_p0[j * HALF + c]) - own);
        }
        spl[t] = m;
    }
    __syncthreads();

    // phase 2: u / cc
    const int c  = tid & 127;
    const int ph = (tid >> 7) * 8;

    float aU[8], aC[8];
#pragma unroll
    for (int pp = 0; pp < 8; pp++) { aU[pp] = 0.f; aC[pp] = sb[c]; }
#pragma unroll 8
    for (int e = 0; e < HALF; e++) {
        float w1 = sW[e * DIM + c];
        float w2 = sW[(HALF + e) * DIM + c];
#pragma unroll
        for (int pp = 0; pp < 8; pp++) {
            aU[pp] = fmaf(sp1[(ph + pp) * HALF + e], w1, aU[pp]);
            aC[pp] = fmaf(spl[(ph + pp) * HALF + e], w2, aC[pp]);
        }
    }
#pragma unroll
    for (int pp = 0; pp < 8; pp++) {
        size_t idx = (size_t)(base + ph + pp) * DIM + c;
        g_u[idx]  = aU[pp];
        g_cc[idx] = aC[pp] - aU[pp];
    }
}

// ---------------- kernel 3: register-direct gather+GELU -> GEMM2 ---------
// Warp owns one point's 16 neighbor-rows. W3b stored k-permuted in smem so
// each lane's A-fragment elements are one contiguous float4 of u / cc.
__global__ void __launch_bounds__(256, 2)
k_mlp(const int* __restrict__ knn,
      const float* __restrict__ W3b, const float* __restrict__ b3b,
      float* __restrict__ out) {
    extern __shared__ char smem[];
    const uint32_t sbase = smem_to_u32(smem);
    const int tid  = threadIdx.x;
    const int wid  = tid >> 5;
    const int lane = tid & 31;

    float* sBb = (float*)(smem + OFF_BB);

    // ---- load + split W3b: stored [n][perm(k)] = W[k][n], bf16 hi/lo ----
    for (int idx = tid; idx < 8192; idx += 256) {
        int n = idx >> 6, ep = idx & 63, k = ep << 1;
        uint32_t off = (uint32_t)n * RS + (uint32_t)perm_pair(k) * 2;
        float b0 = __ldg(&W3b[k * DIM + n]);
        float b1v = __ldg(&W3b[(k + 1) * DIM + n]);
        float rb0, rb1;
        *(uint32_t*)(smem + OFF_WB_HI + off) = split_rn2(b0, b1v, rb0, rb1);
        *(uint32_t*)(smem + OFF_WB_LO + off) = cvt_bf2(rb0, rb1);
    }
    if (tid < 128) sBb[tid] = __ldg(&b3b[tid]);
    __syncthreads();

    const int qr = lane >> 2;            // fragment row group 0..7
    const int qc = (lane & 3) * 2;       // fragment col pair in n-tiles
    const int q4 = (lane & 3) * 4;       // contiguous k base for A gathers
    const uint32_t bOff = ((uint32_t)(lane & 7) + ((uint32_t)(lane >> 4) & 1) * 8) * RS
                        + ((uint32_t)(lane >> 3) & 1) * 16;
    const uint32_t wHi = sbase + OFF_WB_HI + bOff;
    const uint32_t wLo = sbase + OFF_WB_LO + bOff;

    const int gstep = gridDim.x;
    int tile = blockIdx.x;
    int jj = (tile < TILES8) ? __ldg(&knn[(tile * 8 + wid) * KNB + (lane & 15)]) : 0;

    for (; tile < TILES8; tile += gstep) {
        const int i = tile * 8 + wid;    // this warp's point

        // prefetch next tile's neighbor indices
        const int tnext = tile + gstep;
        int jjn = 0;
        if (tnext < TILES8) jjn = __ldg(&knn[(tnext * 8 + wid) * KNB + (lane & 15)]);

        const int j0 = __shfl_sync(0xFFFFFFFF, jj, qr);
        const int j1 = __shfl_sync(0xFFFFFFFF, jj, qr + 8);

        const float* u0 = g_u  + (size_t)j0 * DIM + q4;
        const float* u1 = g_u  + (size_t)j1 * DIM + q4;
        const float* cp = g_cc + (size_t)i  * DIM + q4;

        float acc[16][4];
#pragma unroll
        for (int t = 0; t < 16; t++) { acc[t][0] = acc[t][1] = acc[t][2] = acc[t][3] = 0.f; }

        // prefetch k-step 0
        float4 va = *(const float4*)(u0);
        float4 vb = *(const float4*)(u1);
        float4 vc = *(const float4*)(cp);

#pragma unroll
        for (int ks = 0; ks < 8; ks++) {
            float4 na, nb, nc;
            if (ks < 7) {
                const int kb = (ks + 1) * 16;
                na = *(const float4*)(u0 + kb);
                nb = *(const float4*)(u1 + kb);
                nc = *(const float4*)(cp + kb);
            }
            // h = gelu(u + cc): rows j0 (frag a0/a2) and j1 (a1/a3)
            float h00 = gelu_exact(va.x + vc.x), h01 = gelu_exact(va.y + vc.y);
            float h02 = gelu_exact(va.z + vc.z), h03 = gelu_exact(va.w + vc.w);
            float h10 = gelu_exact(vb.x + vc.x), h11 = gelu_exact(vb.y + vc.y);
            float h12 = gelu_exact(vb.z + vc.z), h13 = gelu_exact(vb.w + vc.w);

            uint32_t aHi[4], aLo[4];
            float r0, r1, r2, r3;
            aHi[0] = split_trunc2(h00, h01, r0, r1);
            aHi[2] = split_trunc2(h02, h03, r2, r3);
            aLo[0] = cvt_bf2(r0, r1);
            aLo[2] = cvt_bf2(r2, r3);
            aHi[1] = split_trunc2(h10, h11, r0, r1);
            aHi[3] = split_trunc2(h12, h13, r2, r3);
            aLo[1] = cvt_bf2(r0, r1);
            aLo[3] = cvt_bf2(r2, r3);

            const uint32_t ka = (uint32_t)ks * 32;
#pragma unroll
            for (int ntp = 0; ntp < 8; ntp++) {
                uint32_t bHi[4], bLo[4];
                ldsm_x4(bHi, wHi + (uint32_t)ntp * 16 * RS + ka);
                ldsm_x4(bLo, wLo + (uint32_t)ntp * 16 * RS + ka);
                mma16816(acc[2 * ntp],     aHi, bHi);
                mma16816(acc[2 * ntp + 1], aHi, bHi + 2);
                mma16816(acc[2 * ntp],     aHi, bLo);
                mma16816(acc[2 * ntp + 1], aHi, bLo + 2);
                mma16816(acc[2 * ntp],     aLo, bHi);
                mma16816(acc[2 * ntp + 1], aLo, bHi + 2);
            }
            va = na; vb = nb; vc = nc;
        }

        // ---- epilogue: +b3b, store (rows qr and qr+8 of this warp) ----
        {
            float* obase = out + ((size_t)i * KNB) * DIM;
#pragma unroll
            for (int nt = 0; nt < 16; nt++) {
                int c = nt * 8 + qc;
                float bb0 = sBb[c], bb1 = sBb[c + 1];
                *(float2*)(obase + (size_t)qr * DIM + c) =
                    make_float2(acc[nt][0] + bb0, acc[nt][1] + bb1);
                *(float2*)(obase + (size_t)(qr + 8) * DIM + c) =
                    make_float2(acc[nt][2] + bb0, acc[nt][3] + bb1);
            }
        }
        jj = jjn;
    }
}

// ---------------- launch ----------------
extern "C" void kernel_launch(void* const* d_in, const int* in_sizes, int n_in,
                              void* d_out, int out_size) {
    const float* xyz = (const float*)d_in[0];
    const int*   knn = (const int*)d_in[1];
    const float* W1  = (const float*)d_in[2];
    const float* b1  = (const float*)d_in[3];
    const float* W2  = (const float*)d_in[4];
    const float* b2  = (const float*)d_in[5];
    const float* W3a = (const float*)d_in[6];
    const float* b3a = (const float*)d_in[7];
    const float* W3b = (const float*)d_in[8];
    const float* b3b = (const float*)d_in[9];
    float* out = (float*)d_out;

    k_p01<<<NPTS / 4, 256>>>(xyz, W1, b1, W2, b2);

    cudaFuncSetAttribute(k_uc, cudaFuncAttributeMaxDynamicSharedMemorySize, UC_SMEM_BYTES);
    k_uc<<<NPTS / 16, 256, UC_SMEM_BYTES>>>(knn, W3a, b3a);

    cudaFuncSetAttribute(k_mlp, cudaFuncAttributeMaxDynamicSharedMemorySize, SMEM_BYTES);
    int dev = 0, sms = 148;
    cudaGetDevice(&dev);
    cudaDeviceGetAttribute(&sms, cudaDevAttrMultiProcessorCount, dev);
    k_mlp<<<2 * sms, 256, SMEM_BYTES>>>(knn, W3b, b3b, out);
}